// round 7
// baseline (speedup 1.0000x reference)
#include <cuda_runtime.h>

#define BB 256
#define TT 2048
#define HH 64
#define NCHUNK (TT / 32)
#define BBTT (BB * TT)

// scratch for per-(dir,b,t) fc dot products: 4 MB
__device__ float g_dot[2 * BBTT];

typedef unsigned long long ull;

__device__ __forceinline__ ull pack2(float lo, float hi) {
    ull r; asm("mov.b64 %0, {%1, %2};" : "=l"(r) : "f"(lo), "f"(hi)); return r;
}
__device__ __forceinline__ void unpack2(ull v, float& lo, float& hi) {
    asm("mov.b64 {%0, %1}, %2;" : "=f"(lo), "=f"(hi) : "l"(v));
}
__device__ __forceinline__ ull fma2(ull a, ull b, ull c) {
    ull d; asm("fma.rn.f32x2 %0, %1, %2, %3;" : "=l"(d) : "l"(a), "l"(b), "l"(c)); return d;
}
__device__ __forceinline__ float tanh_fast(float z) {
    float r; asm("tanh.approx.f32 %0, %1;" : "=f"(r) : "f"(z)); return r;
}

// 4 warps/block, each warp runs TWO chains (same direction -> shared weights).
// 512 chains / 2 = 256 warps = 64 blocks.
__global__ __launch_bounds__(128, 1) void birnn_main(
    const float* __restrict__ x,
    const float* __restrict__ w_ih_f, const float* __restrict__ w_hh_f,
    const float* __restrict__ b_ih_f, const float* __restrict__ b_hh_f,
    const float* __restrict__ w_ih_b, const float* __restrict__ w_hh_b,
    const float* __restrict__ b_ih_b, const float* __restrict__ b_hh_b,
    const float* __restrict__ w_fc,
    float* __restrict__ out)
{
    // per-warp, per-chain double-buffered h (plain 64 floats per phase)
    __shared__ __align__(16) float hbuf[4][2][2][HH];
    __shared__ float pbuf[4][2][32 * 33];   // per-warp, per-chain fc-dot partials

    const int wid  = threadIdx.x >> 5;
    const int lane = threadIdx.x & 31;
    const int gw   = blockIdx.x * 4 + wid;  // 0..255
    const int dir  = gw >> 7;               // 0 = fwd, 1 = bwd
    const int bp   = gw & 127;
    const int bA   = 2 * bp, bB = 2 * bp + 1;

    const float* wih = dir ? w_ih_b : w_ih_f;
    const float* whh = dir ? w_hh_b : w_hh_f;
    const float* bih = dir ? b_ih_b : b_ih_f;
    const float* bhh = dir ? b_hh_b : b_hh_f;

    const int r0 = 2 * lane, r1 = 2 * lane + 1;   // rows owned by this thread

    // --- recurrent weights, k-paired (shared by both chains) ---
    ull wa[32], wb[32];
    {
        const ull* rowA = reinterpret_cast<const ull*>(whh + r0 * HH);
        const ull* rowB = reinterpret_cast<const ull*>(whh + r1 * HH);
#pragma unroll
        for (int m = 0; m < 32; m++) { wa[m] = rowA[m]; wb[m] = rowB[m]; }
    }
    const float wih0 = wih[r0], wih1 = wih[r1];
    const float bias0 = bih[r0] + bhh[r0], bias1 = bih[r1] + bhh[r1];
    const float wf0 = w_fc[r0], wf1 = w_fc[r1];

    // h = 0 into phase 0 for both chains
    reinterpret_cast<float2*>(&hbuf[wid][0][0][0])[lane] = make_float2(0.f, 0.f);
    reinterpret_cast<float2*>(&hbuf[wid][1][0][0])[lane] = make_float2(0.f, 0.f);

    float h0A = 0.f, h1A = 0.f, h0B = 0.f, h1B = 0.f;
    const float* xa = x + bA * TT;
    const float* xbp = x + bB * TT;

    float xcurA = xa [dir ? (TT - 32 + lane) : lane];
    float xcurB = xbp[dir ? (TT - 32 + lane) : lane];

    for (int chunk = 0; chunk < NCHUNK; chunk++) {
        const int tb = dir ? (TT - 1 - chunk * 32) : (chunk * 32);
        int nc = (chunk + 1 < NCHUNK) ? (chunk + 1) : chunk;
        const int nidx = dir ? (TT - 1 - nc * 32 - 31 + lane) : (nc * 32 + lane);
        float xnextA = xa[nidx];
        float xnextB = xbp[nidx];

#define STEP(SS, RD, WR)                                                          \
        {                                                                         \
            const int s = (SS);                                                   \
            const int sl = dir ? (31 - s) : s;                                    \
            float xsA = __shfl_sync(0xffffffffu, xcurA, sl);                      \
            float xsB = __shfl_sync(0xffffffffu, xcurB, sl);                      \
            ull aA = pack2(fmaf(xsA, wih0, bias0), 0.f);                          \
            ull cA = pack2(fmaf(xsA, wih1, bias1), 0.f);                          \
            ull aB = pack2(fmaf(xsB, wih0, bias0), 0.f);                          \
            ull cB = pack2(fmaf(xsB, wih1, bias1), 0.f);                          \
            __syncwarp();                                                         \
            const ulonglong2* hrA =                                               \
                reinterpret_cast<const ulonglong2*>(&hbuf[wid][0][RD][0]);        \
            const ulonglong2* hrB =                                               \
                reinterpret_cast<const ulonglong2*>(&hbuf[wid][1][RD][0]);        \
            _Pragma("unroll")                                                     \
            for (int k = 0; k < 16; k += 2) {                                     \
                ulonglong2 v = hrA[k];                                            \
                ulonglong2 w = hrA[k + 1];                                        \
                aA = fma2(wa[2 * k + 0], v.x, aA);                                \
                cA = fma2(wb[2 * k + 0], v.x, cA);                                \
                aA = fma2(wa[2 * k + 1], v.y, aA);                                \
                cA = fma2(wb[2 * k + 1], v.y, cA);                                \
                aA = fma2(wa[2 * k + 2], w.x, aA);                                \
                cA = fma2(wb[2 * k + 2], w.x, cA);                                \
                aA = fma2(wa[2 * k + 3], w.y, aA);                                \
                cA = fma2(wb[2 * k + 3], w.y, cA);                                \
            }                                                                     \
            _Pragma("unroll")                                                     \
            for (int k = 0; k < 16; k += 2) {                                     \
                ulonglong2 v = hrB[k];                                            \
                ulonglong2 w = hrB[k + 1];                                        \
                aB = fma2(wa[2 * k + 0], v.x, aB);                                \
                cB = fma2(wb[2 * k + 0], v.x, cB);                                \
                aB = fma2(wa[2 * k + 1], v.y, aB);                                \
                cB = fma2(wb[2 * k + 1], v.y, cB);                                \
                aB = fma2(wa[2 * k + 2], w.x, aB);                                \
                cB = fma2(wb[2 * k + 2], w.x, cB);                                \
                aB = fma2(wa[2 * k + 3], w.y, aB);                                \
                cB = fma2(wb[2 * k + 3], w.y, cB);                                \
            }                                                                     \
            float lo, hi;                                                         \
            unpack2(aA, lo, hi);  h0A = tanh_fast(lo + hi);                       \
            unpack2(cA, lo, hi);  h1A = tanh_fast(lo + hi);                       \
            reinterpret_cast<float2*>(&hbuf[wid][0][WR][0])[lane] =               \
                make_float2(h0A, h1A);                                            \
            pbuf[wid][0][s * 33 + lane] = fmaf(h1A, wf1, h0A * wf0);              \
            unpack2(aB, lo, hi);  h0B = tanh_fast(lo + hi);                       \
            unpack2(cB, lo, hi);  h1B = tanh_fast(lo + hi);                       \
            reinterpret_cast<float2*>(&hbuf[wid][1][WR][0])[lane] =               \
                make_float2(h0B, h1B);                                            \
            pbuf[wid][1][s * 33 + lane] = fmaf(h1B, wf1, h0B * wf0);              \
        }

#pragma unroll 1
        for (int s2 = 0; s2 < 16; s2++) {
            STEP(2 * s2,     0, 1)
            STEP(2 * s2 + 1, 1, 0)
        }
#undef STEP

        __syncwarp();
        // transpose-reduce fc partials for both chains
#pragma unroll
        for (int ch = 0; ch < 2; ch++) {
            const float* pr = &pbuf[wid][ch][lane * 33];
            float v[32];
#pragma unroll
            for (int j = 0; j < 32; j++) v[j] = pr[j];
#pragma unroll
            for (int st = 16; st >= 1; st >>= 1)
#pragma unroll
                for (int j = 0; j < 32; j++)
                    if (j < st) v[j] = v[j] + v[j + st];
            int tt = dir ? (tb - lane) : (tb + lane);
            int bb = ch ? bB : bA;
            g_dot[dir * BBTT + bb * TT + tt] = v[0];
        }
        xcurA = xnextA;
        xcurB = xnextB;
    }

    // final hidden states
    reinterpret_cast<float2*>(out + BBTT + dir * (BB * HH) + bA * HH)[lane] =
        make_float2(h0A, h1A);
    reinterpret_cast<float2*>(out + BBTT + dir * (BB * HH) + bB * HH)[lane] =
        make_float2(h0B, h1B);
}

__global__ void birnn_combine(const float* __restrict__ b_fc, float* __restrict__ out)
{
    int i = blockIdx.x * blockDim.x + threadIdx.x;  // 0 .. B*T/4-1
    const float4* df = reinterpret_cast<const float4*>(g_dot);
    const float4* db = reinterpret_cast<const float4*>(g_dot + BBTT);
    float4 f = df[i], g = db[i];
    float bias = b_fc[0];
    float4 o;
    {
        float z, e, r;
        z = 0.5f * (f.x + g.x) + bias;
        asm("ex2.approx.f32 %0, %1;" : "=f"(e) : "f"(-1.4426950408889634f * z));
        asm("rcp.approx.f32 %0, %1;" : "=f"(r) : "f"(1.0f + e));
        o.x = r;
        z = 0.5f * (f.y + g.y) + bias;
        asm("ex2.approx.f32 %0, %1;" : "=f"(e) : "f"(-1.4426950408889634f * z));
        asm("rcp.approx.f32 %0, %1;" : "=f"(r) : "f"(1.0f + e));
        o.y = r;
        z = 0.5f * (f.z + g.z) + bias;
        asm("ex2.approx.f32 %0, %1;" : "=f"(e) : "f"(-1.4426950408889634f * z));
        asm("rcp.approx.f32 %0, %1;" : "=f"(r) : "f"(1.0f + e));
        o.z = r;
        z = 0.5f * (f.w + g.w) + bias;
        asm("ex2.approx.f32 %0, %1;" : "=f"(e) : "f"(-1.4426950408889634f * z));
        asm("rcp.approx.f32 %0, %1;" : "=f"(r) : "f"(1.0f + e));
        o.w = r;
    }
    reinterpret_cast<float4*>(out)[i] = o;
}

extern "C" void kernel_launch(void* const* d_in, const int* in_sizes, int n_in,
                              void* d_out, int out_size)
{
    const float* x      = (const float*)d_in[0];
    const float* w_ih_f = (const float*)d_in[1];
    const float* w_hh_f = (const float*)d_in[2];
    const float* b_ih_f = (const float*)d_in[3];
    const float* b_hh_f = (const float*)d_in[4];
    const float* w_ih_b = (const float*)d_in[5];
    const float* w_hh_b = (const float*)d_in[6];
    const float* b_ih_b = (const float*)d_in[7];
    const float* b_hh_b = (const float*)d_in[8];
    const float* w_fc   = (const float*)d_in[9];
    const float* b_fc   = (const float*)d_in[10];
    float* out = (float*)d_out;

    birnn_main<<<64, 128>>>(x, w_ih_f, w_hh_f, b_ih_f, b_hh_f,
                            w_ih_b, w_hh_b, b_ih_b, b_hh_b, w_fc, out);
    birnn_combine<<<BBTT / 4 / 256, 256>>>(b_fc, out);
}

// round 8
// speedup vs baseline: 1.6639x; 1.6639x over previous
#include <cuda_runtime.h>

#define BB 256
#define TT 2048
#define HH 64
#define NCHUNK (TT / 32)

// scratch for per-(dir,b,t) fc dot products: 4 MB
__device__ float g_dot[2 * BB * TT];

typedef unsigned long long ull;

__device__ __forceinline__ ull pack2(float lo, float hi) {
    ull r; asm("mov.b64 %0, {%1, %2};" : "=l"(r) : "f"(lo), "f"(hi)); return r;
}
__device__ __forceinline__ void unpack2(ull v, float& lo, float& hi) {
    asm("mov.b64 {%0, %1}, %2;" : "=f"(lo), "=f"(hi) : "l"(v));
}
__device__ __forceinline__ ull fma2(ull a, ull b, ull c) {
    ull d; asm("fma.rn.f32x2 %0, %1, %2, %3;" : "=l"(d) : "l"(a), "l"(b), "l"(c)); return d;
}
__device__ __forceinline__ ull add2(ull a, ull b) {
    ull d; asm("add.rn.f32x2 %0, %1, %2;" : "=l"(d) : "l"(a), "l"(b)); return d;
}
__device__ __forceinline__ float tanh_fast(float z) {
    float r; asm("tanh.approx.f32 %0, %1;" : "=f"(r) : "f"(z)); return r;
}
// compiler-only ordering fence: no SASS emitted, blocks reordering of smem ops
__device__ __forceinline__ void cbar() { asm volatile("" ::: "memory"); }

__global__ __launch_bounds__(128, 1) void birnn_main(
    const float* __restrict__ x,
    const float* __restrict__ w_ih_f, const float* __restrict__ w_hh_f,
    const float* __restrict__ b_ih_f, const float* __restrict__ b_hh_f,
    const float* __restrict__ w_ih_b, const float* __restrict__ w_hh_b,
    const float* __restrict__ b_ih_b, const float* __restrict__ b_hh_b,
    const float* __restrict__ w_fc,
    float* __restrict__ out)
{
    // per-warp double-buffered h: plain 64 floats per phase (k-packed consumers)
    __shared__ __align__(16) float hbuf[4][2][HH];
    __shared__ float pbuf[4][32 * 33];   // per-warp fc-dot partials (padded)

    const int wid  = threadIdx.x >> 5;
    const int lane = threadIdx.x & 31;
    const int chain = blockIdx.x * 4 + wid;   // 0..511
    const int dir = chain >> 8;               // 0 = fwd, 1 = bwd
    const int b   = chain & 255;

    const float* wih = dir ? w_ih_b : w_ih_f;
    const float* whh = dir ? w_hh_b : w_hh_f;
    const float* bih = dir ? b_ih_b : b_ih_f;
    const float* bhh = dir ? b_hh_b : b_hh_f;

    const int r0 = 2 * lane, r1 = 2 * lane + 1;   // rows owned by this thread

    // --- recurrent weights, k-paired: wa[m] = (W[r0][2m], W[r0][2m+1]) ---
    ull wa[32], wb[32];
    {
        const ull* rowA = reinterpret_cast<const ull*>(whh + r0 * HH);
        const ull* rowB = reinterpret_cast<const ull*>(whh + r1 * HH);
#pragma unroll
        for (int m = 0; m < 32; m++) { wa[m] = rowA[m]; wb[m] = rowB[m]; }
    }
    const float wihA = wih[r0], wihB = wih[r1];
    const float biasA = bih[r0] + bhh[r0], biasB = bih[r1] + bhh[r1];
    const float wfa = w_fc[r0], wfb = w_fc[r1];

    // h = 0 into phase 0
    reinterpret_cast<float2*>(&hbuf[wid][0][0])[lane] = make_float2(0.f, 0.f);
    cbar();

    float h0 = 0.f, h1 = 0.f;
    const float* xb = x + b * TT;

    // prefetch x for chunk 0
    float xcur = xb[dir ? (TT - 32 + lane) : lane];

    for (int chunk = 0; chunk < NCHUNK; chunk++) {
        const int tb = dir ? (TT - 1 - chunk * 32) : (chunk * 32);
        int nc = (chunk + 1 < NCHUNK) ? (chunk + 1) : chunk;
        float xnext = xb[dir ? (TT - 1 - nc * 32 - 31 + lane) : (nc * 32 + lane)];

        // No per-step __syncwarp: control flow is uniform (no divergence), so the
        // warp issues STS/LDS warp-wide in program order; the full-mask
        // __shfl_sync at each step head keeps the warp converged. cbar() stops
        // the compiler from hoisting the next step's LDS above the h store.
#define STEP(SS, RD, WR)                                                          \
        {                                                                         \
            const int s = (SS);                                                   \
            float xs = __shfl_sync(0xffffffffu, xcur, dir ? (31 - s) : s);        \
            /* fold init (x*w_ih + bias) into accumulator lane 0 */               \
            ull a0 = pack2(fmaf(xs, wihA, biasA), 0.f);                           \
            ull c0 = pack2(fmaf(xs, wihB, biasB), 0.f);                           \
            ull a1 = 0, c1 = 0;                                                   \
            const ulonglong2* hr =                                                \
                reinterpret_cast<const ulonglong2*>(&hbuf[wid][RD][0]);           \
            _Pragma("unroll")                                                     \
            for (int k = 0; k < 16; k += 2) {                                     \
                ulonglong2 v = hr[k];                                             \
                ulonglong2 w = hr[k + 1];                                         \
                a0 = fma2(wa[2 * k + 0], v.x, a0);                                \
                c0 = fma2(wb[2 * k + 0], v.x, c0);                                \
                a1 = fma2(wa[2 * k + 1], v.y, a1);                                \
                c1 = fma2(wb[2 * k + 1], v.y, c1);                                \
                a0 = fma2(wa[2 * k + 2], w.x, a0);                                \
                c0 = fma2(wb[2 * k + 2], w.x, c0);                                \
                a1 = fma2(wa[2 * k + 3], w.y, a1);                                \
                c1 = fma2(wb[2 * k + 3], w.y, c1);                                \
            }                                                                     \
            ull sA = add2(a0, a1);                                                \
            ull sB = add2(c0, c1);                                                \
            float lA, hA, lB, hB;                                                 \
            unpack2(sA, lA, hA);                                                  \
            unpack2(sB, lB, hB);                                                  \
            h0 = tanh_fast(lA + hA);                                              \
            h1 = tanh_fast(lB + hB);                                              \
            reinterpret_cast<float2*>(&hbuf[wid][WR][0])[lane] =                  \
                make_float2(h0, h1);                                              \
            pbuf[wid][s * 33 + lane] = fmaf(h1, wfb, h0 * wfa);                   \
            cbar();                                                               \
        }

#pragma unroll 1
        for (int s2 = 0; s2 < 16; s2++) {
            STEP(2 * s2,     0, 1)
            STEP(2 * s2 + 1, 1, 0)
        }
#undef STEP

        cbar();
        // transpose-reduce fc partials: lane l produces dot for step s=l of this chunk
        // (all pbuf stores are earlier in program order; warp-wide in-order LSU)
        {
            const float* pr = &pbuf[wid][lane * 33];
            float v[32];
#pragma unroll
            for (int j = 0; j < 32; j++) v[j] = pr[j];
#pragma unroll
            for (int st = 16; st >= 1; st >>= 1)
#pragma unroll
                for (int j = 0; j < 32; j++)
                    if (j < st) v[j] = v[j] + v[j + st];
            int tt = dir ? (tb - lane) : (tb + lane);
            g_dot[dir * (BB * TT) + b * TT + tt] = v[0];
        }
        xcur = xnext;
    }

    // final hidden state h_n[dir][b][2l], h_n[dir][b][2l+1]
    reinterpret_cast<float2*>(out + BB * TT + dir * (BB * HH) + b * HH)[lane] =
        make_float2(h0, h1);
}

__global__ void birnn_combine(const float* __restrict__ b_fc, float* __restrict__ out)
{
    int i = blockIdx.x * blockDim.x + threadIdx.x;  // 0 .. B*T/4-1
    const float4* df = reinterpret_cast<const float4*>(g_dot);
    const float4* db = reinterpret_cast<const float4*>(g_dot + BB * TT);
    float4 f = df[i], g = db[i];
    float bias = b_fc[0];
    float4 o;
    {
        float z, e, r;
        z = 0.5f * (f.x + g.x) + bias;
        asm("ex2.approx.f32 %0, %1;" : "=f"(e) : "f"(-1.4426950408889634f * z));
        asm("rcp.approx.f32 %0, %1;" : "=f"(r) : "f"(1.0f + e));
        o.x = r;
        z = 0.5f * (f.y + g.y) + bias;
        asm("ex2.approx.f32 %0, %1;" : "=f"(e) : "f"(-1.4426950408889634f * z));
        asm("rcp.approx.f32 %0, %1;" : "=f"(r) : "f"(1.0f + e));
        o.y = r;
        z = 0.5f * (f.z + g.z) + bias;
        asm("ex2.approx.f32 %0, %1;" : "=f"(e) : "f"(-1.4426950408889634f * z));
        asm("rcp.approx.f32 %0, %1;" : "=f"(r) : "f"(1.0f + e));
        o.z = r;
        z = 0.5f * (f.w + g.w) + bias;
        asm("ex2.approx.f32 %0, %1;" : "=f"(e) : "f"(-1.4426950408889634f * z));
        asm("rcp.approx.f32 %0, %1;" : "=f"(r) : "f"(1.0f + e));
        o.w = r;
    }
    reinterpret_cast<float4*>(out)[i] = o;
}

extern "C" void kernel_launch(void* const* d_in, const int* in_sizes, int n_in,
                              void* d_out, int out_size)
{
    const float* x      = (const float*)d_in[0];
    const float* w_ih_f = (const float*)d_in[1];
    const float* w_hh_f = (const float*)d_in[2];
    const float* b_ih_f = (const float*)d_in[3];
    const float* b_hh_f = (const float*)d_in[4];
    const float* w_ih_b = (const float*)d_in[5];
    const float* w_hh_b = (const float*)d_in[6];
    const float* b_ih_b = (const float*)d_in[7];
    const float* b_hh_b = (const float*)d_in[8];
    const float* w_fc   = (const float*)d_in[9];
    const float* b_fc   = (const float*)d_in[10];
    float* out = (float*)d_out;

    birnn_main<<<128, 128>>>(x, w_ih_f, w_hh_f, b_ih_f, b_hh_f,
                             w_ih_b, w_hh_b, b_ih_b, b_hh_b, w_fc, out);
    birnn_combine<<<(BB * TT) / 4 / 256, 256>>>(b_fc, out);
}

// round 10
// speedup vs baseline: 1.6902x; 1.0158x over previous
#include <cuda_runtime.h>
#include <cuda_fp16.h>

#define BB 256
#define TT 2048
#define HH 64
#define NCHUNK (TT / 32)

// scratch for per-(dir,b,t) fc dot products: 4 MB
__device__ float g_dot[2 * BB * TT];

typedef unsigned long long ull;

__device__ __forceinline__ ull pack2(float lo, float hi) {
    ull r; asm("mov.b64 %0, {%1, %2};" : "=l"(r) : "f"(lo), "f"(hi)); return r;
}
__device__ __forceinline__ void unpack2(ull v, float& lo, float& hi) {
    asm("mov.b64 {%0, %1}, %2;" : "=f"(lo), "=f"(hi) : "l"(v));
}
__device__ __forceinline__ ull fma2(ull a, ull b, ull c) {
    ull d; asm("fma.rn.f32x2 %0, %1, %2, %3;" : "=l"(d) : "l"(a), "l"(b), "l"(c)); return d;
}
__device__ __forceinline__ ull add2(ull a, ull b) {
    ull d; asm("add.rn.f32x2 %0, %1, %2;" : "=l"(d) : "l"(a), "l"(b)); return d;
}
__device__ __forceinline__ float tanh_fast(float z) {
    float r; asm("tanh.approx.f32 %0, %1;" : "=f"(r) : "f"(z)); return r;
}
__device__ __forceinline__ __half2 u2h2(unsigned int u) {
    return *reinterpret_cast<__half2*>(&u);
}
// compiler-only ordering fence
__device__ __forceinline__ void cbar() { asm volatile("" ::: "memory"); }

__global__ __launch_bounds__(128, 1) void birnn_main(
    const float* __restrict__ x,
    const float* __restrict__ w_ih_f, const float* __restrict__ w_hh_f,
    const float* __restrict__ b_ih_f, const float* __restrict__ b_hh_f,
    const float* __restrict__ w_ih_b, const float* __restrict__ w_hh_b,
    const float* __restrict__ b_ih_b, const float* __restrict__ b_hh_b,
    const float* __restrict__ w_fc,
    float* __restrict__ out)
{
    // double-buffered h, k-split: elements 0..31 fp32, 32..63 fp16
    __shared__ __align__(16) float  hbuf32[4][2][32];
    __shared__ __align__(16) __half hbuf16[4][2][32];
    __shared__ float pbuf[4][32 * 33];   // per-warp fc-dot partials (padded)

    const int wid  = threadIdx.x >> 5;
    const int lane = threadIdx.x & 31;
    const int chain = blockIdx.x * 4 + wid;   // 0..511
    const int dir = chain >> 8;               // 0 = fwd, 1 = bwd
    const int b   = chain & 255;

    const float* wih = dir ? w_ih_b : w_ih_f;
    const float* whh = dir ? w_hh_b : w_hh_f;
    const float* bih = dir ? b_ih_b : b_ih_f;
    const float* bhh = dir ? b_hh_b : b_hh_f;

    const int r0 = 2 * lane, r1 = 2 * lane + 1;   // rows owned by this thread

    // --- recurrent weights, k-split ---
    // fp32 part (k = 0..31), k-paired f32x2
    ull wa32[16], wb32[16];
    // fp16 part (k = 32..63), k-paired half2
    __half2 wa16[16], wb16[16];
    {
        const float* rowA = whh + r0 * HH;
        const float* rowB = whh + r1 * HH;
        const ull* rowAu = reinterpret_cast<const ull*>(rowA);
        const ull* rowBu = reinterpret_cast<const ull*>(rowB);
#pragma unroll
        for (int m = 0; m < 16; m++) { wa32[m] = rowAu[m]; wb32[m] = rowBu[m]; }
#pragma unroll
        for (int m = 0; m < 16; m++) {
            wa16[m] = __floats2half2_rn(rowA[32 + 2 * m], rowA[33 + 2 * m]);
            wb16[m] = __floats2half2_rn(rowB[32 + 2 * m], rowB[33 + 2 * m]);
        }
    }
    const float wihA = wih[r0], wihB = wih[r1];
    const float biasA = bih[r0] + bhh[r0], biasB = bih[r1] + bhh[r1];
    const float wfa = w_fc[r0], wfb = w_fc[r1];

    // h = 0 into phase 0
    if (lane < 16) {
        reinterpret_cast<float2*>(&hbuf32[wid][0][0])[lane] = make_float2(0.f, 0.f);
        reinterpret_cast<unsigned int*>(&hbuf16[wid][0][0])[lane] = 0u;
    }
    cbar();

    float h0 = 0.f, h1 = 0.f;
    const float* xb = x + b * TT;
    const __half2 z16 = __floats2half2_rn(0.f, 0.f);

    // prefetch x for chunk 0
    float xcur = xb[dir ? (TT - 32 + lane) : lane];

    for (int chunk = 0; chunk < NCHUNK; chunk++) {
        const int tb = dir ? (TT - 1 - chunk * 32) : (chunk * 32);
        int nc = (chunk + 1 < NCHUNK) ? (chunk + 1) : chunk;
        float xnext = xb[dir ? (TT - 1 - nc * 32 - 31 + lane) : (nc * 32 + lane)];

#define STEP(SS, RD, WR)                                                          \
        {                                                                         \
            const int s = (SS);                                                   \
            float xs = __shfl_sync(0xffffffffu, xcur, dir ? (31 - s) : s);        \
            /* init folded into fp32 accumulator lane 0 */                        \
            ull a0 = pack2(fmaf(xs, wihA, biasA), 0.f);                           \
            ull c0 = pack2(fmaf(xs, wihB, biasB), 0.f);                           \
            ull a1 = 0, c1 = 0;                                                   \
            __half2 p0A = z16, p1A = z16, p0B = z16, p1B = z16;                   \
            const uint4* h16 =                                                    \
                reinterpret_cast<const uint4*>(&hbuf16[wid][RD][0]);              \
            const ulonglong2* h32 =                                               \
                reinterpret_cast<const ulonglong2*>(&hbuf32[wid][RD][0]);         \
            _Pragma("unroll")                                                     \
            for (int k = 0; k < 4; k++) {                                         \
                uint4 v = h16[k];                                                 \
                __half2 q0 = u2h2(v.x), q1 = u2h2(v.y);                           \
                __half2 q2 = u2h2(v.z), q3 = u2h2(v.w);                           \
                p0A = __hfma2(wa16[4 * k + 0], q0, p0A);                          \
                p0B = __hfma2(wb16[4 * k + 0], q0, p0B);                          \
                p1A = __hfma2(wa16[4 * k + 1], q1, p1A);                          \
                p1B = __hfma2(wb16[4 * k + 1], q1, p1B);                          \
                p0A = __hfma2(wa16[4 * k + 2], q2, p0A);                          \
                p0B = __hfma2(wb16[4 * k + 2], q2, p0B);                          \
                p1A = __hfma2(wa16[4 * k + 3], q3, p1A);                          \
                p1B = __hfma2(wb16[4 * k + 3], q3, p1B);                          \
            }                                                                     \
            _Pragma("unroll")                                                     \
            for (int k = 0; k < 8; k += 2) {                                      \
                ulonglong2 v = h32[k];                                            \
                ulonglong2 w = h32[k + 1];                                        \
                a0 = fma2(wa32[2 * k + 0], v.x, a0);                              \
                c0 = fma2(wb32[2 * k + 0], v.x, c0);                              \
                a1 = fma2(wa32[2 * k + 1], v.y, a1);                              \
                c1 = fma2(wb32[2 * k + 1], v.y, c1);                              \
                a0 = fma2(wa32[2 * k + 2], w.x, a0);                              \
                c0 = fma2(wb32[2 * k + 2], w.x, c0);                              \
                a1 = fma2(wa32[2 * k + 3], w.y, a1);                              \
                c1 = fma2(wb32[2 * k + 3], w.y, c1);                              \
            }                                                                     \
            /* fp16 partials -> fp32 BEFORE any full-magnitude add */             \
            float2 qA = __half22float2(__hadd2(p0A, p1A));                        \
            float2 qB = __half22float2(__hadd2(p0B, p1B));                        \
            ull sA = add2(a0, a1);                                                \
            ull sB = add2(c0, c1);                                                \
            float lA, hA, lB, hB;                                                 \
            unpack2(sA, lA, hA);                                                  \
            unpack2(sB, lB, hB);                                                  \
            h0 = tanh_fast((lA + hA) + (qA.x + qA.y));                            \
            h1 = tanh_fast((lB + hB) + (qB.x + qB.y));                            \
            if (lane < 16)                                                        \
                reinterpret_cast<float2*>(&hbuf32[wid][WR][0])[lane] =            \
                    make_float2(h0, h1);                                          \
            else                                                                  \
                reinterpret_cast<__half2*>(&hbuf16[wid][WR][0])[lane - 16] =      \
                    __floats2half2_rn(h0, h1);                                    \
            pbuf[wid][s * 33 + lane] = fmaf(h1, wfb, h0 * wfa);                   \
            cbar();                                                               \
        }

#pragma unroll 1
        for (int s2 = 0; s2 < 16; s2++) {
            STEP(2 * s2,     0, 1)
            STEP(2 * s2 + 1, 1, 0)
        }
#undef STEP

        cbar();
        // transpose-reduce fc partials: lane l produces dot for step s=l of this chunk
        {
            const float* pr = &pbuf[wid][lane * 33];
            float v[32];
#pragma unroll
            for (int j = 0; j < 32; j++) v[j] = pr[j];
#pragma unroll
            for (int st = 16; st >= 1; st >>= 1)
#pragma unroll
                for (int j = 0; j < 32; j++)
                    if (j < st) v[j] = v[j] + v[j + st];
            int tt = dir ? (tb - lane) : (tb + lane);
            g_dot[dir * (BB * TT) + b * TT + tt] = v[0];
        }
        xcur = xnext;
    }

    // final hidden state h_n[dir][b][2l], h_n[dir][b][2l+1] (full fp32 values)
    reinterpret_cast<float2*>(out + BB * TT + dir * (BB * HH) + b * HH)[lane] =
        make_float2(h0, h1);
}

__global__ void birnn_combine(const float* __restrict__ b_fc, float* __restrict__ out)
{
    int i = blockIdx.x * blockDim.x + threadIdx.x;  // 0 .. B*T/4-1
    const float4* df = reinterpret_cast<const float4*>(g_dot);
    const float4* db = reinterpret_cast<const float4*>(g_dot + BB * TT);
    float4 f = df[i], g = db[i];
    float bias = b_fc[0];
    float4 o;
    {
        float z, e, r;
        z = 0.5f * (f.x + g.x) + bias;
        asm("ex2.approx.f32 %0, %1;" : "=f"(e) : "f"(-1.4426950408889634f * z));
        asm("rcp.approx.f32 %0, %1;" : "=f"(r) : "f"(1.0f + e));
        o.x = r;
        z = 0.5f * (f.y + g.y) + bias;
        asm("ex2.approx.f32 %0, %1;" : "=f"(e) : "f"(-1.4426950408889634f * z));
        asm("rcp.approx.f32 %0, %1;" : "=f"(r) : "f"(1.0f + e));
        o.y = r;
        z = 0.5f * (f.z + g.z) + bias;
        asm("ex2.approx.f32 %0, %1;" : "=f"(e) : "f"(-1.4426950408889634f * z));
        asm("rcp.approx.f32 %0, %1;" : "=f"(r) : "f"(1.0f + e));
        o.z = r;
        z = 0.5f * (f.w + g.w) + bias;
        asm("ex2.approx.f32 %0, %1;" : "=f"(e) : "f"(-1.4426950408889634f * z));
        asm("rcp.approx.f32 %0, %1;" : "=f"(r) : "f"(1.0f + e));
        o.w = r;
    }
    reinterpret_cast<float4*>(out)[i] = o;
}

extern "C" void kernel_launch(void* const* d_in, const int* in_sizes, int n_in,
                              void* d_out, int out_size)
{
    const float* x      = (const float*)d_in[0];
    const float* w_ih_f = (const float*)d_in[1];
    const float* w_hh_f = (const float*)d_in[2];
    const float* b_ih_f = (const float*)d_in[3];
    const float* b_hh_f = (const float*)d_in[4];
    const float* w_ih_b = (const float*)d_in[5];
    const float* w_hh_b = (const float*)d_in[6];
    const float* b_ih_b = (const float*)d_in[7];
    const float* b_hh_b = (const float*)d_in[8];
    const float* w_fc   = (const float*)d_in[9];
    const float* b_fc   = (const float*)d_in[10];
    float* out = (float*)d_out;

    birnn_main<<<128, 128>>>(x, w_ih_f, w_hh_f, b_ih_f, b_hh_f,
                             w_ih_b, w_hh_b, b_ih_b, b_hh_b, w_fc, out);
    birnn_combine<<<(BB * TT) / 4 / 256, 256>>>(b_fc, out);
}

// round 11
// speedup vs baseline: 1.7097x; 1.0115x over previous
#include <cuda_runtime.h>
#include <cuda_fp16.h>

#define BB 256
#define TT 2048
#define HH 64
#define NCHUNK (TT / 32)

// scratch for per-(dir,b,t) fc dot products: 4 MB
__device__ float g_dot[2 * BB * TT];

typedef unsigned long long ull;

__device__ __forceinline__ ull pack2(float lo, float hi) {
    ull r; asm("mov.b64 %0, {%1, %2};" : "=l"(r) : "f"(lo), "f"(hi)); return r;
}
__device__ __forceinline__ void unpack2(ull v, float& lo, float& hi) {
    asm("mov.b64 {%0, %1}, %2;" : "=f"(lo), "=f"(hi) : "l"(v));
}
__device__ __forceinline__ ull fma2(ull a, ull b, ull c) {
    ull d; asm("fma.rn.f32x2 %0, %1, %2, %3;" : "=l"(d) : "l"(a), "l"(b), "l"(c)); return d;
}
__device__ __forceinline__ ull add2(ull a, ull b) {
    ull d; asm("add.rn.f32x2 %0, %1, %2;" : "=l"(d) : "l"(a), "l"(b)); return d;
}
__device__ __forceinline__ float tanh_fast(float z) {
    float r; asm("tanh.approx.f32 %0, %1;" : "=f"(r) : "f"(z)); return r;
}
__device__ __forceinline__ __half2 u2h2(unsigned int u) {
    return *reinterpret_cast<__half2*>(&u);
}
// compiler-only ordering fence
__device__ __forceinline__ void cbar() { asm volatile("" ::: "memory"); }

__global__ __launch_bounds__(128, 1) void birnn_main(
    const float* __restrict__ x,
    const float* __restrict__ w_ih_f, const float* __restrict__ w_hh_f,
    const float* __restrict__ b_ih_f, const float* __restrict__ b_hh_f,
    const float* __restrict__ w_ih_b, const float* __restrict__ w_hh_b,
    const float* __restrict__ b_ih_b, const float* __restrict__ b_hh_b,
    const float* __restrict__ w_fc,
    float* __restrict__ out)
{
    // double-buffered h: BOTH buffers hold all 64 rows (branchless dual-store).
    // Consumers read fp32 part from rows 0..31, fp16 part from rows 32..63.
    __shared__ __align__(16) float  hbuf32[4][2][HH];
    __shared__ __align__(16) __half hbuf16[4][2][HH];
    __shared__ float pbuf[4][32 * 33];   // per-warp fc-dot partials (padded)

    const int wid  = threadIdx.x >> 5;
    const int lane = threadIdx.x & 31;
    const int chain = blockIdx.x * 4 + wid;   // 0..511
    const int dir = chain >> 8;               // 0 = fwd, 1 = bwd
    const int b   = chain & 255;

    const float* wih = dir ? w_ih_b : w_ih_f;
    const float* whh = dir ? w_hh_b : w_hh_f;
    const float* bih = dir ? b_ih_b : b_ih_f;
    const float* bhh = dir ? b_hh_b : b_hh_f;

    const int r0 = 2 * lane, r1 = 2 * lane + 1;   // rows owned by this thread

    // --- recurrent weights, k-split ---
    // fp32 part (k = 0..31), k-paired f32x2
    ull wa32[16], wb32[16];
    // fp16 part (k = 32..63), k-paired half2
    __half2 wa16[16], wb16[16];
    {
        const float* rowA = whh + r0 * HH;
        const float* rowB = whh + r1 * HH;
        const ull* rowAu = reinterpret_cast<const ull*>(rowA);
        const ull* rowBu = reinterpret_cast<const ull*>(rowB);
#pragma unroll
        for (int m = 0; m < 16; m++) { wa32[m] = rowAu[m]; wb32[m] = rowBu[m]; }
#pragma unroll
        for (int m = 0; m < 16; m++) {
            wa16[m] = __floats2half2_rn(rowA[32 + 2 * m], rowA[33 + 2 * m]);
            wb16[m] = __floats2half2_rn(rowB[32 + 2 * m], rowB[33 + 2 * m]);
        }
    }
    const float wihA = wih[r0], wihB = wih[r1];
    const float biasA = bih[r0] + bhh[r0], biasB = bih[r1] + bhh[r1];
    const float wfa = w_fc[r0], wfb = w_fc[r1];

    // h = 0 into phase 0 (all lanes, both buffers, no divergence)
    reinterpret_cast<float2*>(&hbuf32[wid][0][0])[lane] = make_float2(0.f, 0.f);
    reinterpret_cast<unsigned int*>(&hbuf16[wid][0][0])[lane] = 0u;
    cbar();

    float h0 = 0.f, h1 = 0.f;
    const float* xb = x + b * TT;
    const __half2 z16 = __floats2half2_rn(0.f, 0.f);

    // prefetch x for chunk 0
    float xcur = xb[dir ? (TT - 32 + lane) : lane];

    for (int chunk = 0; chunk < NCHUNK; chunk++) {
        const int tb = dir ? (TT - 1 - chunk * 32) : (chunk * 32);
        int nc = (chunk + 1 < NCHUNK) ? (chunk + 1) : chunk;
        float xnext = xb[dir ? (TT - 1 - nc * 32 - 31 + lane) : (nc * 32 + lane)];

#define STEP(SS, RD, WR)                                                          \
        {                                                                         \
            const int s = (SS);                                                   \
            float xs = __shfl_sync(0xffffffffu, xcur, dir ? (31 - s) : s);        \
            /* init folded into fp32 accumulator lane 0 */                        \
            ull a0 = pack2(fmaf(xs, wihA, biasA), 0.f);                           \
            ull c0 = pack2(fmaf(xs, wihB, biasB), 0.f);                           \
            ull a1 = 0, c1 = 0;                                                   \
            __half2 p0A = z16, p1A = z16, p0B = z16, p1B = z16;                   \
            const ulonglong2* h32 =                                               \
                reinterpret_cast<const ulonglong2*>(&hbuf32[wid][RD][0]);         \
            const uint4* h16 =                                                    \
                reinterpret_cast<const uint4*>(&hbuf16[wid][RD][32]);             \
            /* fp32 MAC block FIRST: its operand lands earliest (no cvt) */       \
            _Pragma("unroll")                                                     \
            for (int k = 0; k < 8; k += 2) {                                      \
                ulonglong2 v = h32[k];                                            \
                ulonglong2 w = h32[k + 1];                                        \
                a0 = fma2(wa32[2 * k + 0], v.x, a0);                              \
                c0 = fma2(wb32[2 * k + 0], v.x, c0);                              \
                a1 = fma2(wa32[2 * k + 1], v.y, a1);                              \
                c1 = fma2(wb32[2 * k + 1], v.y, c1);                              \
                a0 = fma2(wa32[2 * k + 2], w.x, a0);                              \
                c0 = fma2(wb32[2 * k + 2], w.x, c0);                              \
                a1 = fma2(wa32[2 * k + 3], w.y, a1);                              \
                c1 = fma2(wb32[2 * k + 3], w.y, c1);                              \
            }                                                                     \
            /* fp16 MAC block second: cvt+store latency hidden under fp32 issue */\
            _Pragma("unroll")                                                     \
            for (int k = 0; k < 4; k++) {                                         \
                uint4 v = h16[k];                                                 \
                __half2 q0 = u2h2(v.x), q1 = u2h2(v.y);                           \
                __half2 q2 = u2h2(v.z), q3 = u2h2(v.w);                           \
                p0A = __hfma2(wa16[4 * k + 0], q0, p0A);                          \
                p0B = __hfma2(wb16[4 * k + 0], q0, p0B);                          \
                p1A = __hfma2(wa16[4 * k + 1], q1, p1A);                          \
                p1B = __hfma2(wb16[4 * k + 1], q1, p1B);                          \
                p0A = __hfma2(wa16[4 * k + 2], q2, p0A);                          \
                p0B = __hfma2(wb16[4 * k + 2], q2, p0B);                          \
                p1A = __hfma2(wa16[4 * k + 3], q3, p1A);                          \
                p1B = __hfma2(wb16[4 * k + 3], q3, p1B);                          \
            }                                                                     \
            /* fp16 partials -> fp32 BEFORE any full-magnitude add */             \
            float2 qA = __half22float2(__hadd2(p0A, p1A));                        \
            float2 qB = __half22float2(__hadd2(p0B, p1B));                        \
            ull sA = add2(a0, a1);                                                \
            ull sB = add2(c0, c1);                                                \
            float lA, hA, lB, hB;                                                 \
            unpack2(sA, lA, hA);                                                  \
            unpack2(sB, lB, hB);                                                  \
            h0 = tanh_fast((lA + hA) + (qA.x + qA.y));                            \
            h1 = tanh_fast((lB + hB) + (qB.x + qB.y));                            \
            /* branchless dual store: every lane writes both formats */           \
            reinterpret_cast<float2*>(&hbuf32[wid][WR][0])[lane] =                \
                make_float2(h0, h1);                                              \
            reinterpret_cast<__half2*>(&hbuf16[wid][WR][0])[lane] =               \
                __floats2half2_rn(h0, h1);                                        \
            pbuf[wid][s * 33 + lane] = fmaf(h1, wfb, h0 * wfa);                   \
            cbar();                                                               \
        }

#pragma unroll 1
        for (int s2 = 0; s2 < 16; s2++) {
            STEP(2 * s2,     0, 1)
            STEP(2 * s2 + 1, 1, 0)
        }
#undef STEP

        cbar();
        // transpose-reduce fc partials: lane l produces dot for step s=l of this chunk
        {
            const float* pr = &pbuf[wid][lane * 33];
            float v[32];
#pragma unroll
            for (int j = 0; j < 32; j++) v[j] = pr[j];
#pragma unroll
            for (int st = 16; st >= 1; st >>= 1)
#pragma unroll
                for (int j = 0; j < 32; j++)
                    if (j < st) v[j] = v[j] + v[j + st];
            int tt = dir ? (tb - lane) : (tb + lane);
            g_dot[dir * (BB * TT) + b * TT + tt] = v[0];
        }
        xcur = xnext;
    }

    // final hidden state h_n[dir][b][2l], h_n[dir][b][2l+1] (full fp32 values)
    reinterpret_cast<float2*>(out + BB * TT + dir * (BB * HH) + b * HH)[lane] =
        make_float2(h0, h1);
}

__global__ void birnn_combine(const float* __restrict__ b_fc, float* __restrict__ out)
{
    int i = blockIdx.x * blockDim.x + threadIdx.x;  // 0 .. B*T/4-1
    const float4* df = reinterpret_cast<const float4*>(g_dot);
    const float4* db = reinterpret_cast<const float4*>(g_dot + BB * TT);
    float4 f = df[i], g = db[i];
    float bias = b_fc[0];
    float4 o;
    {
        float z, e, r;
        z = 0.5f * (f.x + g.x) + bias;
        asm("ex2.approx.f32 %0, %1;" : "=f"(e) : "f"(-1.4426950408889634f * z));
        asm("rcp.approx.f32 %0, %1;" : "=f"(r) : "f"(1.0f + e));
        o.x = r;
        z = 0.5f * (f.y + g.y) + bias;
        asm("ex2.approx.f32 %0, %1;" : "=f"(e) : "f"(-1.4426950408889634f * z));
        asm("rcp.approx.f32 %0, %1;" : "=f"(r) : "f"(1.0f + e));
        o.y = r;
        z = 0.5f * (f.z + g.z) + bias;
        asm("ex2.approx.f32 %0, %1;" : "=f"(e) : "f"(-1.4426950408889634f * z));
        asm("rcp.approx.f32 %0, %1;" : "=f"(r) : "f"(1.0f + e));
        o.z = r;
        z = 0.5f * (f.w + g.w) + bias;
        asm("ex2.approx.f32 %0, %1;" : "=f"(e) : "f"(-1.4426950408889634f * z));
        asm("rcp.approx.f32 %0, %1;" : "=f"(r) : "f"(1.0f + e));
        o.w = r;
    }
    reinterpret_cast<float4*>(out)[i] = o;
}

extern "C" void kernel_launch(void* const* d_in, const int* in_sizes, int n_in,
                              void* d_out, int out_size)
{
    const float* x      = (const float*)d_in[0];
    const float* w_ih_f = (const float*)d_in[1];
    const float* w_hh_f = (const float*)d_in[2];
    const float* b_ih_f = (const float*)d_in[3];
    const float* b_hh_f = (const float*)d_in[4];
    const float* w_ih_b = (const float*)d_in[5];
    const float* w_hh_b = (const float*)d_in[6];
    const float* b_ih_b = (const float*)d_in[7];
    const float* b_hh_b = (const float*)d_in[8];
    const float* w_fc   = (const float*)d_in[9];
    const float* b_fc   = (const float*)d_in[10];
    float* out = (float*)d_out;

    birnn_main<<<128, 128>>>(x, w_ih_f, w_hh_f, b_ih_f, b_hh_f,
                             w_ih_b, w_hh_b, b_ih_b, b_hh_b, w_fc, out);
    birnn_combine<<<(BB * TT) / 4 / 256, 256>>>(b_fc, out);
}

// round 12
// speedup vs baseline: 1.8453x; 1.0793x over previous
#include <cuda_runtime.h>
#include <cuda_fp16.h>

#define BB 256
#define TT 2048
#define HH 64
#define NCHUNK (TT / 32)

// scratch for per-(dir,b,t) fc dot products: 4 MB
__device__ float g_dot[2 * BB * TT];

typedef unsigned long long ull;

__device__ __forceinline__ ull pack2(float lo, float hi) {
    ull r; asm("mov.b64 %0, {%1, %2};" : "=l"(r) : "f"(lo), "f"(hi)); return r;
}
__device__ __forceinline__ void unpack2(ull v, float& lo, float& hi) {
    asm("mov.b64 {%0, %1}, %2;" : "=f"(lo), "=f"(hi) : "l"(v));
}
__device__ __forceinline__ ull fma2(ull a, ull b, ull c) {
    ull d; asm("fma.rn.f32x2 %0, %1, %2, %3;" : "=l"(d) : "l"(a), "l"(b), "l"(c)); return d;
}
__device__ __forceinline__ ull add2(ull a, ull b) {
    ull d; asm("add.rn.f32x2 %0, %1, %2;" : "=l"(d) : "l"(a), "l"(b)); return d;
}
__device__ __forceinline__ float tanh_fast(float z) {
    float r; asm("tanh.approx.f32 %0, %1;" : "=f"(r) : "f"(z)); return r;
}
__device__ __forceinline__ __half2 u2h2(unsigned int u) {
    return *reinterpret_cast<__half2*>(&u);
}
// compiler-only ordering fence
__device__ __forceinline__ void cbar() { asm volatile("" ::: "memory"); }

__global__ __launch_bounds__(128, 1) void birnn_main(
    const float* __restrict__ x,
    const float* __restrict__ w_ih_f, const float* __restrict__ w_hh_f,
    const float* __restrict__ b_ih_f, const float* __restrict__ b_hh_f,
    const float* __restrict__ w_ih_b, const float* __restrict__ w_hh_b,
    const float* __restrict__ b_ih_b, const float* __restrict__ b_hh_b,
    const float* __restrict__ w_fc,
    float* __restrict__ out)
{
    // double-buffered h: BOTH buffers hold all 64 rows (branchless dual-store).
    // Consumers read fp32 part from rows 0..15, fp16 part from rows 16..63.
    __shared__ __align__(16) float  hbuf32[4][2][HH];
    __shared__ __align__(16) __half hbuf16[4][2][HH];
    __shared__ float pbuf[4][32 * 33];   // per-warp fc-dot partials (padded)

    const int wid  = threadIdx.x >> 5;
    const int lane = threadIdx.x & 31;
    const int chain = blockIdx.x * 4 + wid;   // 0..511
    const int dir = chain >> 8;               // 0 = fwd, 1 = bwd
    const int b   = chain & 255;

    const float* wih = dir ? w_ih_b : w_ih_f;
    const float* whh = dir ? w_hh_b : w_hh_f;
    const float* bih = dir ? b_ih_b : b_ih_f;
    const float* bhh = dir ? b_hh_b : b_hh_f;

    const int r0 = 2 * lane, r1 = 2 * lane + 1;   // rows owned by this thread

    // --- recurrent weights, k-split 16/48 ---
    // fp32 part (k = 0..15), k-paired f32x2
    ull wa32[8], wb32[8];
    // fp16 part (k = 16..63), k-paired half2
    __half2 wa16[24], wb16[24];
    {
        const float* rowA = whh + r0 * HH;
        const float* rowB = whh + r1 * HH;
        const ull* rowAu = reinterpret_cast<const ull*>(rowA);
        const ull* rowBu = reinterpret_cast<const ull*>(rowB);
#pragma unroll
        for (int m = 0; m < 8; m++) { wa32[m] = rowAu[m]; wb32[m] = rowBu[m]; }
#pragma unroll
        for (int m = 0; m < 24; m++) {
            wa16[m] = __floats2half2_rn(rowA[16 + 2 * m], rowA[17 + 2 * m]);
            wb16[m] = __floats2half2_rn(rowB[16 + 2 * m], rowB[17 + 2 * m]);
        }
    }
    const float wihA = wih[r0], wihB = wih[r1];
    const float biasA = bih[r0] + bhh[r0], biasB = bih[r1] + bhh[r1];
    const float wfa = w_fc[r0], wfb = w_fc[r1];

    // h = 0 into phase 0 (all lanes, both buffers, no divergence)
    reinterpret_cast<float2*>(&hbuf32[wid][0][0])[lane] = make_float2(0.f, 0.f);
    reinterpret_cast<unsigned int*>(&hbuf16[wid][0][0])[lane] = 0u;
    cbar();

    float h0 = 0.f, h1 = 0.f;
    const float* xb = x + b * TT;
    const __half2 z16 = __floats2half2_rn(0.f, 0.f);

    // prefetch x for chunk 0
    float xcur = xb[dir ? (TT - 32 + lane) : lane];

    for (int chunk = 0; chunk < NCHUNK; chunk++) {
        const int tb = dir ? (TT - 1 - chunk * 32) : (chunk * 32);
        int nc = (chunk + 1 < NCHUNK) ? (chunk + 1) : chunk;
        float xnext = xb[dir ? (TT - 1 - nc * 32 - 31 + lane) : (nc * 32 + lane)];

#define STEP(SS, RD, WR)                                                          \
        {                                                                         \
            const int s = (SS);                                                   \
            float xs = __shfl_sync(0xffffffffu, xcur, dir ? (31 - s) : s);        \
            /* init folded into fp32 accumulator lane 0 */                        \
            ull a0 = pack2(fmaf(xs, wihA, biasA), 0.f);                           \
            ull c0 = pack2(fmaf(xs, wihB, biasB), 0.f);                           \
            ull a1 = 0, c1 = 0;                                                   \
            __half2 p0A = z16, p1A = z16, p0B = z16, p1B = z16;                   \
            const ulonglong2* h32 =                                               \
                reinterpret_cast<const ulonglong2*>(&hbuf32[wid][RD][0]);         \
            const uint4* h16 =                                                    \
                reinterpret_cast<const uint4*>(&hbuf16[wid][RD][16]);             \
            /* fp32 MAC block FIRST: its operand lands earliest (no cvt) */       \
            _Pragma("unroll")                                                     \
            for (int k = 0; k < 4; k += 2) {                                      \
                ulonglong2 v = h32[k];                                            \
                ulonglong2 w = h32[k + 1];                                        \
                a0 = fma2(wa32[2 * k + 0], v.x, a0);                              \
                c0 = fma2(wb32[2 * k + 0], v.x, c0);                              \
                a1 = fma2(wa32[2 * k + 1], v.y, a1);                              \
                c1 = fma2(wb32[2 * k + 1], v.y, c1);                              \
                a0 = fma2(wa32[2 * k + 2], w.x, a0);                              \
                c0 = fma2(wb32[2 * k + 2], w.x, c0);                              \
                a1 = fma2(wa32[2 * k + 3], w.y, a1);                              \
                c1 = fma2(wb32[2 * k + 3], w.y, c1);                              \
            }                                                                     \
            /* fp16 MAC block second: cvt+store latency hidden under fp32 issue */\
            _Pragma("unroll")                                                     \
            for (int k = 0; k < 6; k++) {                                         \
                uint4 v = h16[k];                                                 \
                __half2 q0 = u2h2(v.x), q1 = u2h2(v.y);                           \
                __half2 q2 = u2h2(v.z), q3 = u2h2(v.w);                           \
                p0A = __hfma2(wa16[4 * k + 0], q0, p0A);                          \
                p0B = __hfma2(wb16[4 * k + 0], q0, p0B);                          \
                p1A = __hfma2(wa16[4 * k + 1], q1, p1A);                          \
                p1B = __hfma2(wb16[4 * k + 1], q1, p1B);                          \
                p0A = __hfma2(wa16[4 * k + 2], q2, p0A);                          \
                p0B = __hfma2(wb16[4 * k + 2], q2, p0B);                          \
                p1A = __hfma2(wa16[4 * k + 3], q3, p1A);                          \
                p1B = __hfma2(wb16[4 * k + 3], q3, p1B);                          \
            }                                                                     \
            /* fp16 partials -> fp32 BEFORE any full-magnitude add */             \
            float2 qA = __half22float2(__hadd2(p0A, p1A));                        \
            float2 qB = __half22float2(__hadd2(p0B, p1B));                        \
            ull sA = add2(a0, a1);                                                \
            ull sB = add2(c0, c1);                                                \
            float lA, hA, lB, hB;                                                 \
            unpack2(sA, lA, hA);                                                  \
            unpack2(sB, lB, hB);                                                  \
            h0 = tanh_fast((lA + hA) + (qA.x + qA.y));                            \
            h1 = tanh_fast((lB + hB) + (qB.x + qB.y));                            \
            /* branchless dual store: every lane writes both formats */           \
            reinterpret_cast<float2*>(&hbuf32[wid][WR][0])[lane] =                \
                make_float2(h0, h1);                                              \
            reinterpret_cast<__half2*>(&hbuf16[wid][WR][0])[lane] =               \
                __floats2half2_rn(h0, h1);                                        \
            pbuf[wid][s * 33 + lane] = fmaf(h1, wfb, h0 * wfa);                   \
            cbar();                                                               \
        }

#pragma unroll 1
        for (int s2 = 0; s2 < 16; s2++) {
            STEP(2 * s2,     0, 1)
            STEP(2 * s2 + 1, 1, 0)
        }
#undef STEP

        cbar();
        // transpose-reduce fc partials: lane l produces dot for step s=l of this chunk
        {
            const float* pr = &pbuf[wid][lane * 33];
            float v[32];
#pragma unroll
            for (int j = 0; j < 32; j++) v[j] = pr[j];
#pragma unroll
            for (int st = 16; st >= 1; st >>= 1)
#pragma unroll
                for (int j = 0; j < 32; j++)
                    if (j < st) v[j] = v[j] + v[j + st];
            int tt = dir ? (tb - lane) : (tb + lane);
            g_dot[dir * (BB * TT) + b * TT + tt] = v[0];
        }
        xcur = xnext;
    }

    // final hidden state h_n[dir][b][2l], h_n[dir][b][2l+1] (full fp32 values)
    reinterpret_cast<float2*>(out + BB * TT + dir * (BB * HH) + b * HH)[lane] =
        make_float2(h0, h1);
}

__global__ void birnn_combine(const float* __restrict__ b_fc, float* __restrict__ out)
{
    int i = blockIdx.x * blockDim.x + threadIdx.x;  // 0 .. B*T/4-1
    const float4* df = reinterpret_cast<const float4*>(g_dot);
    const float4* db = reinterpret_cast<const float4*>(g_dot + BB * TT);
    float4 f = df[i], g = db[i];
    float bias = b_fc[0];
    float4 o;
    {
        float z, e, r;
        z = 0.5f * (f.x + g.x) + bias;
        asm("ex2.approx.f32 %0, %1;" : "=f"(e) : "f"(-1.4426950408889634f * z));
        asm("rcp.approx.f32 %0, %1;" : "=f"(r) : "f"(1.0f + e));
        o.x = r;
        z = 0.5f * (f.y + g.y) + bias;
        asm("ex2.approx.f32 %0, %1;" : "=f"(e) : "f"(-1.4426950408889634f * z));
        asm("rcp.approx.f32 %0, %1;" : "=f"(r) : "f"(1.0f + e));
        o.y = r;
        z = 0.5f * (f.z + g.z) + bias;
        asm("ex2.approx.f32 %0, %1;" : "=f"(e) : "f"(-1.4426950408889634f * z));
        asm("rcp.approx.f32 %0, %1;" : "=f"(r) : "f"(1.0f + e));
        o.z = r;
        z = 0.5f * (f.w + g.w) + bias;
        asm("ex2.approx.f32 %0, %1;" : "=f"(e) : "f"(-1.4426950408889634f * z));
        asm("rcp.approx.f32 %0, %1;" : "=f"(r) : "f"(1.0f + e));
        o.w = r;
    }
    reinterpret_cast<float4*>(out)[i] = o;
}

extern "C" void kernel_launch(void* const* d_in, const int* in_sizes, int n_in,
                              void* d_out, int out_size)
{
    const float* x      = (const float*)d_in[0];
    const float* w_ih_f = (const float*)d_in[1];
    const float* w_hh_f = (const float*)d_in[2];
    const float* b_ih_f = (const float*)d_in[3];
    const float* b_hh_f = (const float*)d_in[4];
    const float* w_ih_b = (const float*)d_in[5];
    const float* w_hh_b = (const float*)d_in[6];
    const float* b_ih_b = (const float*)d_in[7];
    const float* b_hh_b = (const float*)d_in[8];
    const float* w_fc   = (const float*)d_in[9];
    const float* b_fc   = (const float*)d_in[10];
    float* out = (float*)d_out;

    birnn_main<<<128, 128>>>(x, w_ih_f, w_hh_f, b_ih_f, b_hh_f,
                             w_ih_b, w_hh_b, b_ih_b, b_hh_b, w_fc, out);
    birnn_combine<<<(BB * TT) / 4 / 256, 256>>>(b_fc, out);
}